// round 1
// baseline (speedup 1.0000x reference)
#include <cuda_runtime.h>
#include <math.h>

#define NNODES 8192
#define NEDGES 262144
#define NFEAT  64

// ---------------- static scratch (allowed: __device__ globals) ----------------
__device__ unsigned int g_winner[67108864];   // 8192*8192, zero-init, reset each launch
__device__ float g_deg[NNODES];
__device__ float g_dinv[NNODES];
__device__ float g_cr[NNODES];                // 1 - dinv^2
__device__ int   g_rowcnt[NNODES];
__device__ int   g_rowptr[NNODES + 1];
__device__ int   g_fill[NNODES];
__device__ int   g_col[NEDGES];
__device__ float g_val[NEDGES];
__device__ float g_tx1[NNODES * NFEAT];
__device__ float g_tx2[NNODES * NFEAT];
__device__ int   g_is64;

// ---------------- edge loader robust to int32/int64 edge_index ----------------
__device__ __forceinline__ void load_edge(const void* ei, int e, int& r, int& c) {
    if (g_is64) {
        const long long* p = (const long long*)ei;
        r = (int)p[e];
        c = (int)p[NEDGES + e];
    } else {
        const int* p = (const int*)ei;
        r = p[e];
        c = p[NEDGES + e];
    }
}

__device__ __forceinline__ float sigmoid_gate(const float* adw) {
    return 1.0f / (1.0f + expf(-adw[0]));
}

// K0: zero per-launch accumulators + detect edge_index dtype
__global__ void k_init(const void* ei) {
    int i = blockIdx.x * blockDim.x + threadIdx.x;
    if (i < NNODES) {
        g_deg[i] = 0.0f;
        g_rowcnt[i] = 0;
        g_fill[i] = 0;
    }
    if (i == 0) {
        // if data is int64, the high 32-bit words (odd int32 slots) are all zero.
        // if int32, those slots are uniform in [0,8192): P(128 zeros) ~ 8192^-128.
        const int* p = (const int*)ei;
        int is64 = 1;
        #pragma unroll 1
        for (int k = 0; k < 128; k++) {
            if (p[2 * k + 1] != 0) { is64 = 0; break; }
        }
        g_is64 = is64;
    }
}

// K1: last-write-wins dedup: winner[key] = max edge index + 1
__global__ void k_dedup(const void* ei) {
    int e = blockIdx.x * blockDim.x + threadIdx.x;
    if (e >= NEDGES) return;
    int r, c;
    load_edge(ei, e, r, c);
    atomicMax(&g_winner[(unsigned)r * NNODES + c], (unsigned)(e + 1));
}

// K2: degree (row sums of deduped A) + per-row winning-edge counts
__global__ void k_degcnt(const void* ei, const float* ew, const float* adw) {
    int e = blockIdx.x * blockDim.x + threadIdx.x;
    if (e >= NEDGES) return;
    int r, c;
    load_edge(ei, e, r, c);
    if (g_winner[(unsigned)r * NNODES + c] == (unsigned)(e + 1)) {
        float aw = ew[e] * sigmoid_gate(adw);
        atomicAdd(&g_deg[r], aw);
        atomicAdd(&g_rowcnt[r], 1);
    }
}

// K3: d^{-1/2} and diagonal coefficient of L (self-loop folded in)
__global__ void k_dinv() {
    int i = blockIdx.x * blockDim.x + threadIdx.x;
    if (i >= NNODES) return;
    float d = 1.0f + g_deg[i];           // +1 from the added identity
    float di = rsqrtf(d);                // deg >= 1, never inf
    g_dinv[i] = di;
    g_cr[i] = 1.0f - di * di;            // 1 - dinv[r]*A_rr*dinv[r], A_rr(self)=1
}

// K4: exclusive scan of row counts -> row_ptr (single block, 8 elems/thread)
__global__ void k_scan() {
    __shared__ int sh[1024];
    int t = threadIdx.x;
    int base = t * 8;
    int loc[8];
    int sum = 0;
    #pragma unroll
    for (int i = 0; i < 8; i++) { loc[i] = g_rowcnt[base + i]; sum += loc[i]; }
    sh[t] = sum;
    __syncthreads();
    for (int off = 1; off < 1024; off <<= 1) {
        int v = (t >= off) ? sh[t - off] : 0;
        __syncthreads();
        if (t >= off) sh[t] += v;
        __syncthreads();
    }
    int run = sh[t] - sum;   // exclusive prefix
    #pragma unroll
    for (int i = 0; i < 8; i++) { g_rowptr[base + i] = run; run += loc[i]; }
    if (t == 1023) g_rowptr[NNODES] = run;
}

// K5: scatter winning edges into CSR with fully scaled values
__global__ void k_scatter(const void* ei, const float* ew, const float* adw) {
    int e = blockIdx.x * blockDim.x + threadIdx.x;
    if (e >= NEDGES) return;
    int r, c;
    load_edge(ei, e, r, c);
    if (g_winner[(unsigned)r * NNODES + c] == (unsigned)(e + 1)) {
        float aw = ew[e] * sigmoid_gate(adw);
        int pos = g_rowptr[r] + atomicAdd(&g_fill[r], 1);
        g_col[pos] = c;
        g_val[pos] = g_dinv[r] * aw * g_dinv[c];
    }
}

// K6: reset only the touched winner cells (keeps the 256MB array all-zero)
__global__ void k_reset(const void* ei) {
    int e = blockIdx.x * blockDim.x + threadIdx.x;
    if (e >= NEDGES) return;
    int r, c;
    load_edge(ei, e, r, c);
    g_winner[(unsigned)r * NNODES + c] = 0u;
}

// K7/K8: warp-per-row CSR SpMM.
// mode 0: Tx1 = L @ X           = cr[r]*X[r]   - sum val*X[c]
// mode 1: Tx2 = 2*(L@Tx1) - X   = 2*(cr[r]*Tx1[r] - sum val*Tx1[c]) - X[r]
__global__ void k_spmm(const float* __restrict__ x, int mode) {
    int gw = (blockIdx.x * blockDim.x + threadIdx.x) >> 5;   // row
    int lane = threadIdx.x & 31;
    if (gw >= NNODES) return;

    const float2* Y2 = (mode == 0) ? (const float2*)x : (const float2*)g_tx1;
    float2 yr = Y2[gw * 32 + lane];
    float cr = g_cr[gw];
    float ax = cr * yr.x;
    float ay = cr * yr.y;

    int beg = g_rowptr[gw];
    int end = g_rowptr[gw + 1];
    #pragma unroll 4
    for (int i = beg; i < end; i++) {
        int c = g_col[i];
        float v = g_val[i];
        float2 yc = Y2[c * 32 + lane];
        ax -= v * yc.x;
        ay -= v * yc.y;
    }

    float2 o;
    if (mode == 0) {
        o.x = ax; o.y = ay;
        ((float2*)g_tx1)[gw * 32 + lane] = o;
    } else {
        const float2* X2 = (const float2*)x;
        float2 xs = X2[gw * 32 + lane];
        o.x = 2.0f * ax - xs.x;
        o.y = 2.0f * ay - xs.y;
        ((float2*)g_tx2)[gw * 32 + lane] = o;
    }
}

// K9: out = X@W0 + Tx1@W1 + Tx2@W2 + bias.  Block: 8 rows x 64 cols.
__global__ void k_out(const float* __restrict__ x, const float* __restrict__ W,
                      const float* __restrict__ bias, float* __restrict__ out) {
    __shared__ float xc[8][192];
    int j = threadIdx.x;       // 0..63 output column
    int rl = threadIdx.y;      // 0..7 row within block
    int r0 = blockIdx.x * 8;

    int t = rl * 64 + j;       // 0..511
    for (int idx = t; idx < 8 * 192; idx += 512) {
        int rr = idx / 192;
        int ii = idx % 192;
        int row = r0 + rr;
        float v;
        if (ii < 64)       v = x[row * 64 + ii];
        else if (ii < 128) v = g_tx1[row * 64 + (ii - 64)];
        else               v = g_tx2[row * 64 + (ii - 128)];
        xc[rr][ii] = v;
    }
    __syncthreads();

    float acc = bias[j];
    #pragma unroll
    for (int i = 0; i < 64; i++) acc += xc[rl][i]       * W[i * 64 + j];
    #pragma unroll
    for (int i = 0; i < 64; i++) acc += xc[rl][64 + i]  * W[4096 + i * 64 + j];
    #pragma unroll
    for (int i = 0; i < 64; i++) acc += xc[rl][128 + i] * W[8192 + i * 64 + j];

    out[(r0 + rl) * 64 + j] = acc;
}

extern "C" void kernel_launch(void* const* d_in, const int* in_sizes, int n_in,
                              void* d_out, int out_size) {
    const float* x    = (const float*)d_in[0];
    const void*  ei   = d_in[1];                 // int64 or int32, auto-detected
    const float* ew   = (const float*)d_in[2];
    const float* W    = (const float*)d_in[3];   // [3][64][64]
    const float* adw  = (const float*)d_in[4];
    const float* bias = (const float*)d_in[5];
    float* out = (float*)d_out;

    const int EB = NEDGES / 256;   // 1024 blocks for edge-parallel kernels

    k_init<<<32, 256>>>(ei);
    k_dedup<<<EB, 256>>>(ei);
    k_degcnt<<<EB, 256>>>(ei, ew, adw);
    k_dinv<<<32, 256>>>();
    k_scan<<<1, 1024>>>();
    k_scatter<<<EB, 256>>>(ei, ew, adw);
    k_reset<<<EB, 256>>>(ei);
    k_spmm<<<NNODES * 32 / 256, 256>>>(x, 0);    // Tx1 = L @ X
    k_spmm<<<NNODES * 32 / 256, 256>>>(x, 1);    // Tx2 = 2*(L@Tx1) - X
    k_out<<<NNODES / 8, dim3(64, 8)>>>(x, W, bias, out);
}

// round 5
// speedup vs baseline: 1.5503x; 1.5503x over previous
#include <cuda_runtime.h>
#include <math.h>

#define NNODES 8192
#define NEDGES 262144
#define NFEAT  64

#define TBITS  21
#define TSIZE  (1u << TBITS)     // 2M slots * 8B = 16MB, L2-resident
#define TMASK  (TSIZE - 1u)

// ---------------- static scratch (allowed: __device__ globals) ----------------
__device__ unsigned long long g_table[TSIZE];   // zero-init; cleared by sweep each launch
__device__ float g_deg[NNODES];                 // sum of raw ew of winning edges per row
__device__ float g_dinv[NNODES];
__device__ float g_cr[NNODES];                  // 1 - dinv^2 (diagonal coeff of L)
__device__ int   g_rowcnt[NNODES];
__device__ int   g_rowptr[NNODES + 1];
__device__ int   g_fill[NNODES];
__device__ int   g_col[NEDGES];
__device__ float g_val[NEDGES];
__device__ float g_tx1[NNODES * NFEAT];
__device__ int   g_is64;
__device__ float g_gate;

// ---------------- edge loader robust to int32/int64 edge_index ----------------
__device__ __forceinline__ void load_edge(const void* ei, int e, int& r, int& c) {
    if (g_is64) {
        const long long* p = (const long long*)ei;
        r = (int)p[e];
        c = (int)p[NEDGES + e];
    } else {
        const int* p = (const int*)ei;
        r = p[e];
        c = p[NEDGES + e];
    }
}

// K0: zero per-launch accumulators + detect edge_index dtype
__global__ void k_init(const void* ei) {
    int i = blockIdx.x * blockDim.x + threadIdx.x;
    if (i < NNODES) {
        g_deg[i] = 0.0f;
        g_rowcnt[i] = 0;
        g_fill[i] = 0;
    }
    if (i == 0) {
        // int64 data => odd 32-bit words all zero; int32 => uniform in [0,8192)
        const int* p = (const int*)ei;
        int is64 = 1;
        #pragma unroll 1
        for (int k = 0; k < 128; k++) {
            if (p[2 * k + 1] != 0) { is64 = 0; break; }
        }
        g_is64 = is64;
    }
}

// K1: hash insert with last-write-wins + incremental degree/count.
// Slot value: (key << 32) | (edge_index + 1). Key = r*8192 + c (26 bits).
// Key field is immutable once a slot is claimed, so same-key resolution via
// atomicMax compares edge indices; different keys probe linearly.
// Degree stays exact under races: each displacement adds (ew[new] - ew[old]),
// telescoping to ew[final winner] regardless of interleaving.
__global__ void k_insert(const void* ei, const float* __restrict__ ew) {
    int e = blockIdx.x * blockDim.x + threadIdx.x;
    if (e >= NEDGES) return;
    int r, c;
    load_edge(ei, e, r, c);
    unsigned key = ((unsigned)r << 13) | (unsigned)c;
    unsigned long long desired = ((unsigned long long)key << 32) | (unsigned)(e + 1);
    unsigned slot = (key * 0x9E3779B1u) >> (32 - TBITS);

    while (true) {
        unsigned long long cur = g_table[slot];
        if (cur == 0ULL) {
            unsigned long long old = atomicCAS(&g_table[slot], 0ULL, desired);
            if (old == 0ULL) {
                atomicAdd(&g_deg[r], ew[e]);     // fresh cell: current winner
                atomicAdd(&g_rowcnt[r], 1);
                return;
            }
            cur = old;
        }
        if ((unsigned)(cur >> 32) == key) {
            unsigned long long old = atomicMax(&g_table[slot], desired);
            if (old < desired) {
                int oe = (int)(unsigned)old - 1; // displaced previous winner
                atomicAdd(&g_deg[r], ew[e] - ew[oe]);
            }
            return;
        }
        slot = (slot + 1) & TMASK;
    }
}

// K2: fused gate + d^{-1/2} + diagonal coeff + exclusive scan of row counts.
__global__ void k_prep(const float* __restrict__ adw) {
    __shared__ int sh[1024];
    int t = threadIdx.x;
    float gate = 1.0f / (1.0f + __expf(-adw[0]));
    if (t == 0) g_gate = gate;

    int base = t * 8;
    int loc[8];
    int sum = 0;
    #pragma unroll
    for (int i = 0; i < 8; i++) {
        int row = base + i;
        float d = 1.0f + gate * g_deg[row];     // +1 from identity self-loop
        float di = rsqrtf(d);                   // d >= 1, never inf
        g_dinv[row] = di;
        g_cr[row] = 1.0f - di * di;
        loc[i] = g_rowcnt[row];
        sum += loc[i];
    }
    sh[t] = sum;
    __syncthreads();
    for (int off = 1; off < 1024; off <<= 1) {
        int v = (t >= off) ? sh[t - off] : 0;
        __syncthreads();
        if (t >= off) sh[t] += v;
        __syncthreads();
    }
    int run = sh[t] - sum;   // exclusive prefix
    #pragma unroll
    for (int i = 0; i < 8; i++) { g_rowptr[base + i] = run; run += loc[i]; }
    if (t == 1023) g_rowptr[NNODES] = run;
}

// K3: slot-parallel sweep: emit CSR entries for final winners AND clear table.
__global__ void k_sweep(const float* __restrict__ ew) {
    unsigned s = blockIdx.x * blockDim.x + threadIdx.x;
    unsigned long long v = g_table[s];
    if (v == 0ULL) return;
    g_table[s] = 0ULL;                            // table clean for next replay
    unsigned key = (unsigned)(v >> 32);
    int e = (int)(unsigned)v - 1;
    int r = (int)(key >> 13);
    int c = (int)(key & 8191u);
    int pos = g_rowptr[r] + atomicAdd(&g_fill[r], 1);
    g_col[pos] = c;
    g_val[pos] = g_gate * ew[e] * g_dinv[r] * g_dinv[c];
}

// K4: warp-per-row CSR SpMM:  Tx1 = L @ X = cr[r]*X[r] - sum val*X[c]
__global__ void k_spmm1(const float* __restrict__ x) {
    int gw = (blockIdx.x * blockDim.x + threadIdx.x) >> 5;   // row
    int lane = threadIdx.x & 31;
    if (gw >= NNODES) return;

    const float2* Y2 = (const float2*)x;
    float2 yr = Y2[gw * 32 + lane];
    float cr = g_cr[gw];
    float ax = cr * yr.x;
    float ay = cr * yr.y;

    int beg = g_rowptr[gw];
    int end = g_rowptr[gw + 1];
    #pragma unroll 4
    for (int i = beg; i < end; i++) {
        int c = g_col[i];
        float v = g_val[i];
        float2 yc = Y2[c * 32 + lane];
        ax -= v * yc.x;
        ay -= v * yc.y;
    }
    float2 o; o.x = ax; o.y = ay;
    ((float2*)g_tx1)[gw * 32 + lane] = o;
}

// K5: fused second SpMM + output GEMM.
// Block = 8 warps; warp w computes Tx2[r0+w] = 2*(L@Tx1)[row] - X[row] into
// shared, then all 256 threads do the [8x192]@[192x64] GEMM + bias.
__global__ void k_spmm2_out(const float* __restrict__ x, const float* __restrict__ W,
                            const float* __restrict__ bias, float* __restrict__ out) {
    __shared__ float xc[8][192];
    int tid = threadIdx.x;
    int w = tid >> 5;
    int lane = tid & 31;
    int r0 = blockIdx.x * 8;
    int row = r0 + w;

    const float2* X2 = (const float2*)x;
    const float2* T2 = (const float2*)g_tx1;
    float2 xs = X2[row * 32 + lane];
    float2 t1 = T2[row * 32 + lane];
    float cr = g_cr[row];
    float ax = cr * t1.x;
    float ay = cr * t1.y;

    int beg = g_rowptr[row];
    int end = g_rowptr[row + 1];
    #pragma unroll 4
    for (int i = beg; i < end; i++) {
        int c = g_col[i];
        float v = g_val[i];
        float2 yc = T2[c * 32 + lane];
        ax -= v * yc.x;
        ay -= v * yc.y;
    }

    xc[w][2 * lane]           = xs.x;
    xc[w][2 * lane + 1]       = xs.y;
    xc[w][64 + 2 * lane]      = t1.x;
    xc[w][64 + 2 * lane + 1]  = t1.y;
    xc[w][128 + 2 * lane]     = 2.0f * ax - xs.x;   // Tx2
    xc[w][128 + 2 * lane + 1] = 2.0f * ay - xs.y;
    __syncthreads();

    int j = tid & 63;          // output column
    int rl = tid >> 6;         // 0..3 -> handles rows rl and rl+4
    float acc0 = bias[j];
    float acc1 = acc0;
    #pragma unroll
    for (int i = 0; i < 64; i++) {
        float wv = W[i * 64 + j];
        acc0 += xc[rl][i] * wv;
        acc1 += xc[rl + 4][i] * wv;
    }
    #pragma unroll
    for (int i = 0; i < 64; i++) {
        float wv = W[4096 + i * 64 + j];
        acc0 += xc[rl][64 + i] * wv;
        acc1 += xc[rl + 4][64 + i] * wv;
    }
    #pragma unroll
    for (int i = 0; i < 64; i++) {
        float wv = W[8192 + i * 64 + j];
        acc0 += xc[rl][128 + i] * wv;
        acc1 += xc[rl + 4][128 + i] * wv;
    }
    out[(r0 + rl) * 64 + j] = acc0;
    out[(r0 + rl + 4) * 64 + j] = acc1;
}

extern "C" void kernel_launch(void* const* d_in, const int* in_sizes, int n_in,
                              void* d_out, int out_size) {
    const float* x    = (const float*)d_in[0];
    const void*  ei   = d_in[1];                 // int64 or int32, auto-detected
    const float* ew   = (const float*)d_in[2];
    const float* W    = (const float*)d_in[3];   // [3][64][64]
    const float* adw  = (const float*)d_in[4];
    const float* bias = (const float*)d_in[5];
    float* out = (float*)d_out;

    k_init<<<32, 256>>>(ei);
    k_insert<<<NEDGES / 256, 256>>>(ei, ew);
    k_prep<<<1, 1024>>>(adw);
    k_sweep<<<TSIZE / 256, 256>>>(ew);
    k_spmm1<<<NNODES * 32 / 256, 256>>>(x);              // Tx1 = L @ X
    k_spmm2_out<<<NNODES / 8, 256>>>(x, W, bias, out);   // Tx2 + GEMM + bias
}